// round 4
// baseline (speedup 1.0000x reference)
#include <cuda_runtime.h>
#include <cuda_fp16.h>
#include <cstdint>

// ---------------------------------------------------------------------------
// Problem constants
// ---------------------------------------------------------------------------
#define N_IN    8192
#define N_OUT   256
#define BATCH   1024
#define LEVELS  2
#define K_TOTAL (LEVELS * N_IN * 16)          // 262144 ; k = (l*8192+i)*16 + c
#define NKSTEPS (K_TOTAL / 16)                // 16384 ; kstep = one (l,i)
#define KSPLIT  18
#define KSTEPS_PER ((NKSTEPS + KSPLIT - 1) / KSPLIT)  // 911
#define MTILES  (BATCH / 128)                 // 8

// Scratch (__device__ globals: no runtime allocation)
__device__ __half   g_B [(size_t)N_OUT * K_TOTAL];          // [j][k]   134 MB
__device__ unsigned g_mc[(size_t)LEVELS * BATCH * N_IN];    // (c<<16)|mag_fp16
__device__ float    g_part[(size_t)KSPLIT * BATCH * N_OUT]; // split-K partials

// ---------------------------------------------------------------------------
// prep_B: B[j][k=(li*16+c)] = sign(w[16l+c, i, j]) * mask[i,j]   (fp16-exact)
// block = (l,i), thread = j ; all w reads coalesced over j.
// ---------------------------------------------------------------------------
__global__ void __launch_bounds__(256) prep_B_kernel(const float* __restrict__ w,
                                                     const float* __restrict__ mask) {
    int li = blockIdx.x;                     // l*8192 + i
    int l  = li >> 13;
    int i  = li & (N_IN - 1);
    int j  = threadIdx.x;
    float m = mask[(size_t)i * N_OUT + j];
    unsigned r[8];
#pragma unroll
    for (int p = 0; p < 8; ++p) {
        float v0 = w[((size_t)(16 * l + 2 * p)     * N_IN + i) * N_OUT + j];
        float v1 = w[((size_t)(16 * l + 2 * p + 1) * N_IN + i) * N_OUT + j];
        float s0 = (v0 > 0.f) ? m : ((v0 < 0.f) ? -m : 0.f);
        float s1 = (v1 > 0.f) ? m : ((v1 < 0.f) ? -m : 0.f);
        r[p] = (unsigned)__half_as_ushort(__float2half_rn(s0)) |
               ((unsigned)__half_as_ushort(__float2half_rn(s1)) << 16);
    }
    uint4* d = (uint4*)(g_B + (size_t)j * K_TOTAL + ((size_t)li << 4));
    d[0] = make_uint4(r[0], r[1], r[2], r[3]);
    d[1] = make_uint4(r[4], r[5], r[6], r[7]);
}

// ---------------------------------------------------------------------------
// prep_x: mc[l][b][i] = (c<<16) | fp16(|s0*s1*s2*s3|)
// c = (s0<0)<<3 | (s1<0)<<2 | (s2<0)<<1 | (s3<0)   (reference bit order: x = MSB)
// block per (l,b) so the 32KB x-row stays cache-hot for the 3 random gathers.
// ---------------------------------------------------------------------------
__global__ void __launch_bounds__(256) prep_x_kernel(const float* __restrict__ x,
                                                     const int* __restrict__ rm0,
                                                     const int* __restrict__ rm1,
                                                     const int* __restrict__ rm2) {
    int lb = blockIdx.x;
    const float* row = x + (size_t)lb * N_IN;
    unsigned* mp = g_mc + (size_t)lb * N_IN;
    for (int i = threadIdx.x; i < N_IN; i += blockDim.x) {
        float s0 = row[i];
        float s1 = row[rm0[i]];
        float s2 = row[rm1[i]];
        float s3 = row[rm2[i]];
        unsigned c = ((s0 < 0.f) ? 8u : 0u) | ((s1 < 0.f) ? 4u : 0u) |
                     ((s2 < 0.f) ? 2u : 0u) | ((s3 < 0.f) ? 1u : 0u);
        unsigned mh = __half_as_ushort(__float2half_rn(fabsf(s0 * s1 * s2 * s3)));
        mp[i] = (c << 16) | mh;
    }
}

// ---------------------------------------------------------------------------
// HMMA main kernel. grid = (MTILES=8, KSPLIT=18); block = 512 (16 warps).
// CTA tile: M=128, N=256. warp (wm = warp>>3, wn = warp&7): 64(M) x 32(N).
// Per kstep (one i): A fragments generated in registers from g_mc (one-hot),
// B fragments LDG'd straight from g_B (L2-shared across the 8 M-tile CTAs).
// No shared memory in the hot path.
// ---------------------------------------------------------------------------
__device__ __forceinline__ void mma16816(float* d, unsigned a0, unsigned a1,
                                         unsigned a2, unsigned a3,
                                         unsigned b0, unsigned b1) {
    asm volatile(
        "mma.sync.aligned.m16n8k16.row.col.f32.f16.f16.f32 "
        "{%0,%1,%2,%3}, {%4,%5,%6,%7}, {%8,%9}, {%0,%1,%2,%3};"
        : "+f"(d[0]), "+f"(d[1]), "+f"(d[2]), "+f"(d[3])
        : "r"(a0), "r"(a1), "r"(a2), "r"(a3), "r"(b0), "r"(b1));
}

__global__ void __launch_bounds__(512, 1) main_kernel() {
    const int tid  = threadIdx.x;
    const int warp = tid >> 5, lane = tid & 31;
    const int g = lane >> 2, t = lane & 3;
    const int warp_m = warp >> 3, warp_n = warp & 7;
    const int bm = blockIdx.x * 128 + warp_m * 64;   // batch-row base of warp
    const int jn = warp_n * 32;                      // out-col base of warp
    const int ks0 = blockIdx.y * KSTEPS_PER;
    const int ks1 = min(NKSTEPS, ks0 + KSTEPS_PER);
    const int nk  = ks1 - ks0;

    float acc[4][4][4];                              // [m16 blk][n8 frag][4]
#pragma unroll
    for (int a = 0; a < 4; ++a)
#pragma unroll
        for (int b = 0; b < 4; ++b)
#pragma unroll
            for (int d = 0; d < 4; ++d) acc[a][b][d] = 0.f;

    // B: frag f covers cols jn+f*8 .. +8 ; lane reads col jn+f*8+g,
    // b0 = halves (k0+2t, k0+2t+1), b1 = +8.  Row stride = K_TOTAL halves.
    const __half* Bbase = g_B + (size_t)(jn + g) * K_TOTAL + (size_t)ks0 * 16 + 2 * t;

    auto ldB = [&](unsigned* B, int krel) {
        const __half* p = Bbase + (size_t)krel * 16;
#pragma unroll
        for (int f = 0; f < 4; ++f) {
            const __half* q = p + (size_t)f * 8 * K_TOTAL;
            B[2 * f]     = __ldg((const unsigned*)q);
            B[2 * f + 1] = __ldg((const unsigned*)(q + 8));
        }
    };

    auto ldMC = [&](unsigned* mc, int ki) {
        int l = ki >> 13, i = ki & (N_IN - 1);
        const unsigned* p = g_mc + ((size_t)l * BATCH + bm + g) * N_IN + i;
#pragma unroll
        for (int blk = 0; blk < 4; ++blk) {
            mc[2 * blk]     = __ldg(p + (size_t)(blk * 16)     * N_IN);
            mc[2 * blk + 1] = __ldg(p + (size_t)(blk * 16 + 8) * N_IN);
        }
    };

    // One-hot A-frag gen + 16 MMAs for one kstep.
    auto step = [&](const unsigned* mc, const unsigned* B) {
#pragma unroll
        for (int blk = 0; blk < 4; ++blk) {
            unsigned m0 = mc[2 * blk], m1 = mc[2 * blk + 1];
            unsigned c0 = m0 >> 16,    c1 = m1 >> 16;
            unsigned v0 = (c0 & 1u) ? (m0 << 16) : (m0 & 0xFFFFu);
            unsigned v1 = (c1 & 1u) ? (m1 << 16) : (m1 & 0xFFFFu);
            unsigned h0 = c0 >> 1,     h1 = c1 >> 1;
            unsigned a0 = (h0 == (unsigned)t)       ? v0 : 0u;
            unsigned a1 = (h1 == (unsigned)t)       ? v1 : 0u;
            unsigned a2 = (h0 == (unsigned)(t + 4)) ? v0 : 0u;
            unsigned a3 = (h1 == (unsigned)(t + 4)) ? v1 : 0u;
#pragma unroll
            for (int f = 0; f < 4; ++f)
                mma16816(acc[blk][f], a0, a1, a2, a3, B[2 * f], B[2 * f + 1]);
        }
    };

    // 2-deep register ping-pong: loads for kstep+1 issued before MMAs of kstep.
    unsigned B0[8], B1[8], M0[8], M1[8];
    ldB(B0, 0);
    ldMC(M0, ks0);
    int k2 = 0;
    for (;;) {
        if (k2 + 1 < nk) { ldB(B1, k2 + 1); ldMC(M1, ks0 + k2 + 1); }
        step(M0, B0);
        if (k2 + 1 >= nk) break;
        if (k2 + 2 < nk) { ldB(B0, k2 + 2); ldMC(M0, ks0 + k2 + 2); }
        step(M1, B1);
        if (k2 + 2 >= nk) break;
        k2 += 2;
    }

    // Epilogue: write split-K partial tile (no atomics).
    float* pp = g_part + (size_t)blockIdx.y * BATCH * N_OUT;
#pragma unroll
    for (int blk = 0; blk < 4; ++blk) {
        int r0 = bm + blk * 16 + g, r1 = r0 + 8;
#pragma unroll
        for (int f = 0; f < 4; ++f) {
            int j0 = jn + f * 8 + 2 * t;
            *(float2*)&pp[(size_t)r0 * N_OUT + j0] =
                make_float2(acc[blk][f][0], acc[blk][f][1]);
            *(float2*)&pp[(size_t)r1 * N_OUT + j0] =
                make_float2(acc[blk][f][2], acc[blk][f][3]);
        }
    }
}

// ---------------------------------------------------------------------------
// reduce: out = |gamma| * sum over KSPLIT partials
// ---------------------------------------------------------------------------
__global__ void __launch_bounds__(256) reduce_kernel(const float* __restrict__ gamma,
                                                     float* __restrict__ out) {
    size_t idx = (size_t)blockIdx.x * 256 + threadIdx.x;
    float s = 0.f;
#pragma unroll
    for (int p = 0; p < KSPLIT; ++p)
        s += g_part[(size_t)p * BATCH * N_OUT + idx];
    out[idx] = s * fabsf(gamma[0]);
}

// ---------------------------------------------------------------------------
// launch — inputs: x f32[2,1024,8192], w f32[32,8192,256], gamma f32[1],
// pruning_mask f32[8192,256], rand_map_0/1/2 i32[8192]. out f32[1024,256].
// ---------------------------------------------------------------------------
extern "C" void kernel_launch(void* const* d_in, const int* in_sizes, int n_in,
                              void* d_out, int out_size) {
    const float* x     = (const float*)d_in[0];
    const float* w     = (const float*)d_in[1];
    const float* gamma = (const float*)d_in[2];
    const float* mask  = (const float*)d_in[3];
    const int*   rm0   = (const int*)d_in[4];
    const int*   rm1   = (const int*)d_in[5];
    const int*   rm2   = (const int*)d_in[6];
    float* out = (float*)d_out;

    prep_B_kernel<<<LEVELS * N_IN, 256>>>(w, mask);
    prep_x_kernel<<<LEVELS * BATCH, 256>>>(x, rm0, rm1, rm2);
    main_kernel<<<dim3(MTILES, KSPLIT), 512>>>();
    reduce_kernel<<<(BATCH * N_OUT) / 256, 256>>>(gamma, out);
}

// round 5
// speedup vs baseline: 1.7285x; 1.7285x over previous
#include <cuda_runtime.h>
#include <cuda_fp16.h>
#include <cstdint>

// ---------------------------------------------------------------------------
// Problem constants
// ---------------------------------------------------------------------------
#define N_IN    8192
#define N_OUT   256
#define BATCH   1024
#define LEVELS  2
#define NKSTEPS (LEVELS * N_IN)               // 16384 ; kstep = (l,i), 16 k each
#define KSPLIT  18
#define KSTEPS_PER ((NKSTEPS + KSPLIT - 1) / KSPLIT)  // 911
#define MTILES  (BATCH / 128)                 // 8

// Scratch (__device__ globals: no runtime allocation)
// g_B[kstep][j][p] : p = permuted truth-table index so lane t's uint2 at byte
//                    8t is exactly the mma.m16n8k16 B fragment (b0,b1).
__device__ __half   g_B  [(size_t)NKSTEPS * N_OUT * 16];      // 134 MB
__device__ unsigned g_mc0[(size_t)LEVELS * BATCH * N_IN];     // [l][b][i] tmp
__device__ unsigned g_mcT[(size_t)LEVELS * N_IN * BATCH];     // [l][i][bperm]
__device__ float    g_part[(size_t)KSPLIT * BATCH * N_OUT];   // split-K partials

// ---------------------------------------------------------------------------
// prep_B: for kstep (l,i), thread j:  s[c] = sign(w[16l+c,i,j]) * mask[i,j]
// stored in permuted order {0,1,8,9, 2,3,10,11, 4,5,12,13, 6,7,14,15}.
// ---------------------------------------------------------------------------
__global__ void __launch_bounds__(256) prep_B_kernel(const float* __restrict__ w,
                                                     const float* __restrict__ mask) {
    const int ki = blockIdx.x;               // l*8192 + i
    const int l  = ki >> 13;
    const int i  = ki & (N_IN - 1);
    const int j  = threadIdx.x;
    const float m = mask[(size_t)i * N_OUT + j];
    float s[16];
#pragma unroll
    for (int c = 0; c < 16; ++c) {
        float v = w[((size_t)(16 * l + c) * N_IN + i) * N_OUT + j];
        s[c] = (v > 0.f) ? m : ((v < 0.f) ? -m : 0.f);
    }
    const int perm[16] = {0, 1, 8, 9, 2, 3, 10, 11, 4, 5, 12, 13, 6, 7, 14, 15};
    unsigned r[8];
#pragma unroll
    for (int p = 0; p < 8; ++p) {
        unsigned lo = __half_as_ushort(__float2half_rn(s[perm[2 * p]]));
        unsigned hi = __half_as_ushort(__float2half_rn(s[perm[2 * p + 1]]));
        r[p] = lo | (hi << 16);
    }
    uint4* d = (uint4*)(g_B + ((size_t)ki * N_OUT + j) * 16);
    d[0] = make_uint4(r[0], r[1], r[2], r[3]);
    d[1] = make_uint4(r[4], r[5], r[6], r[7]);
}

// ---------------------------------------------------------------------------
// prep_x: mc0[l][b][i] = (c<<16) | fp16(|s0*s1*s2*s3|)
// c = (s0<0)<<3 | (s1<0)<<2 | (s2<0)<<1 | (s3<0)
// block per (l,b): the 32KB x-row stays cache-hot for the 3 random gathers.
// ---------------------------------------------------------------------------
__global__ void __launch_bounds__(256) prep_x_kernel(const float* __restrict__ x,
                                                     const int* __restrict__ rm0,
                                                     const int* __restrict__ rm1,
                                                     const int* __restrict__ rm2) {
    int lb = blockIdx.x;
    const float* row = x + (size_t)lb * N_IN;
    unsigned* mp = g_mc0 + (size_t)lb * N_IN;
    for (int i = threadIdx.x; i < N_IN; i += blockDim.x) {
        float s0 = row[i];
        float s1 = row[rm0[i]];
        float s2 = row[rm1[i]];
        float s3 = row[rm2[i]];
        unsigned c = ((s0 < 0.f) ? 8u : 0u) | ((s1 < 0.f) ? 4u : 0u) |
                     ((s2 < 0.f) ? 2u : 0u) | ((s3 < 0.f) ? 1u : 0u);
        unsigned mh = __half_as_ushort(__float2half_rn(fabsf(s0 * s1 * s2 * s3)));
        mp[i] = (c << 16) | mh;
    }
}

// ---------------------------------------------------------------------------
// transpose mc0 [l][b][i] -> mcT [l][i][bperm],
// bperm = (b&~15) | ((b&7)<<1) | ((b>>3)&1)  so rows g and g+8 are adjacent
// (one broadcast uint2 LDG per m16 block in the main loop).
// ---------------------------------------------------------------------------
__global__ void __launch_bounds__(256) transpose_mc_kernel() {
    __shared__ unsigned tile[32][33];
    const int l  = blockIdx.z;
    const int b0 = blockIdx.y * 32;
    const int i0 = blockIdx.x * 32;
    const int tx = threadIdx.x, ty = threadIdx.y;
#pragma unroll
    for (int r = ty; r < 32; r += 8)
        tile[r][tx] = g_mc0[((size_t)l * BATCH + b0 + r) * N_IN + i0 + tx];
    __syncthreads();
#pragma unroll
    for (int r = ty; r < 32; r += 8) {
        int b  = b0 + tx;
        int bp = (b & ~15) | ((b & 7) << 1) | ((b >> 3) & 1);
        g_mcT[((size_t)l * N_IN + i0 + r) * BATCH + bp] = tile[tx][r];
    }
}

// ---------------------------------------------------------------------------
// HMMA main kernel. grid = (MTILES=8, KSPLIT=18); block = 512 (16 warps).
// CTA tile M=128 x N=256; warp tile 64(M) x 32(N).
// All hot-loop loads fully coalesced: B = 4x LDG.64 (256B/warp contiguous),
// mc = 4x broadcast LDG.64 (64B/warp). A fragments built in registers
// (one-hot over the truth table). No shared memory in the hot path.
// ---------------------------------------------------------------------------
__device__ __forceinline__ void mma16816(float* d, unsigned a0, unsigned a1,
                                         unsigned a2, unsigned a3,
                                         unsigned b0, unsigned b1) {
    asm volatile(
        "mma.sync.aligned.m16n8k16.row.col.f32.f16.f16.f32 "
        "{%0,%1,%2,%3}, {%4,%5,%6,%7}, {%8,%9}, {%0,%1,%2,%3};"
        : "+f"(d[0]), "+f"(d[1]), "+f"(d[2]), "+f"(d[3])
        : "r"(a0), "r"(a1), "r"(a2), "r"(a3), "r"(b0), "r"(b1));
}

__global__ void __launch_bounds__(512, 1) main_kernel() {
    const int tid  = threadIdx.x;
    const int warp = tid >> 5, lane = tid & 31;
    const int g = lane >> 2, t = lane & 3;
    const int warp_m = warp >> 3, warp_n = warp & 7;
    const int bm = blockIdx.x * 128 + warp_m * 64;   // batch-row base of warp
    const int jn = warp_n * 32;                      // out-col base of warp
    const int ks0 = blockIdx.y * KSTEPS_PER;
    const int nk  = min(NKSTEPS, ks0 + KSTEPS_PER) - ks0;

    float acc[4][4][4];                              // [m16 blk][n8 frag][4]
#pragma unroll
    for (int a = 0; a < 4; ++a)
#pragma unroll
        for (int b = 0; b < 4; ++b)
#pragma unroll
            for (int d = 0; d < 4; ++d) acc[a][b][d] = 0.f;

    // B fragment pointer: uint2 = 4 permuted halves; +t -> this lane's (b0,b1).
    // row stride = 4 uint2 ; f stride = 8 rows = 32 uint2 ; kstep = 1024 uint2.
    const uint2* Bp =
        (const uint2*)(g_B + ((size_t)ks0 * N_OUT + jn + g) * 16) + t;
    // mc pointer: uint2 at bperm index (blk*16 + 2g) -> rows (g, g+8).
    const unsigned* Mp = g_mcT + (size_t)ks0 * BATCH + bm + 2 * g;

    auto ldB = [&](uint2* B, int krel) {
        const uint2* p = Bp + (size_t)krel * (N_OUT * 4);
#pragma unroll
        for (int f = 0; f < 4; ++f) B[f] = __ldg(p + f * 32);
    };
    auto ldMC = [&](uint2* M, int krel) {
        const unsigned* p = Mp + (size_t)krel * BATCH;
#pragma unroll
        for (int blk = 0; blk < 4; ++blk)
            M[blk] = __ldg((const uint2*)(p + blk * 16));
    };

    auto step = [&](const uint2* M, const uint2* B) {
#pragma unroll
        for (int blk = 0; blk < 4; ++blk) {
            unsigned m0 = M[blk].x, m1 = M[blk].y;   // rows g, g+8
            unsigned c0 = m0 >> 16,  c1 = m1 >> 16;
            unsigned v0 = (c0 & 1u) ? (m0 << 16) : (m0 & 0xFFFFu);
            unsigned v1 = (c1 & 1u) ? (m1 << 16) : (m1 & 0xFFFFu);
            unsigned h0 = c0 >> 1,   h1 = c1 >> 1;
            unsigned a0 = (h0 == (unsigned)t)       ? v0 : 0u;
            unsigned a1 = (h1 == (unsigned)t)       ? v1 : 0u;
            unsigned a2 = (h0 == (unsigned)(t + 4)) ? v0 : 0u;
            unsigned a3 = (h1 == (unsigned)(t + 4)) ? v1 : 0u;
#pragma unroll
            for (int f = 0; f < 4; ++f)
                mma16816(acc[blk][f], a0, a1, a2, a3, B[f].x, B[f].y);
        }
    };

    // 2-deep register ping-pong.
    uint2 B0[4], B1[4], M0[4], M1[4];
    ldB(B0, 0);
    ldMC(M0, 0);
    int k2 = 0;
    for (;;) {
        if (k2 + 1 < nk) { ldB(B1, k2 + 1); ldMC(M1, k2 + 1); }
        step(M0, B0);
        if (k2 + 1 >= nk) break;
        if (k2 + 2 < nk) { ldB(B0, k2 + 2); ldMC(M0, k2 + 2); }
        step(M1, B1);
        if (k2 + 2 >= nk) break;
        k2 += 2;
    }

    // Epilogue: split-K partial tile (no atomics).
    float* pp = g_part + (size_t)blockIdx.y * BATCH * N_OUT;
#pragma unroll
    for (int blk = 0; blk < 4; ++blk) {
        int r0 = bm + blk * 16 + g, r1 = r0 + 8;
#pragma unroll
        for (int f = 0; f < 4; ++f) {
            int j0 = jn + f * 8 + 2 * t;
            *(float2*)&pp[(size_t)r0 * N_OUT + j0] =
                make_float2(acc[blk][f][0], acc[blk][f][1]);
            *(float2*)&pp[(size_t)r1 * N_OUT + j0] =
                make_float2(acc[blk][f][2], acc[blk][f][3]);
        }
    }
}

// ---------------------------------------------------------------------------
// reduce: out = |gamma| * sum over KSPLIT partials
// ---------------------------------------------------------------------------
__global__ void __launch_bounds__(256) reduce_kernel(const float* __restrict__ gamma,
                                                     float* __restrict__ out) {
    size_t idx = (size_t)blockIdx.x * 256 + threadIdx.x;
    float s = 0.f;
#pragma unroll
    for (int p = 0; p < KSPLIT; ++p)
        s += g_part[(size_t)p * BATCH * N_OUT + idx];
    out[idx] = s * fabsf(gamma[0]);
}

// ---------------------------------------------------------------------------
// launch — inputs: x f32[2,1024,8192], w f32[32,8192,256], gamma f32[1],
// pruning_mask f32[8192,256], rand_map_0/1/2 i32[8192]. out f32[1024,256].
// ---------------------------------------------------------------------------
extern "C" void kernel_launch(void* const* d_in, const int* in_sizes, int n_in,
                              void* d_out, int out_size) {
    const float* x     = (const float*)d_in[0];
    const float* w     = (const float*)d_in[1];
    const float* gamma = (const float*)d_in[2];
    const float* mask  = (const float*)d_in[3];
    const int*   rm0   = (const int*)d_in[4];
    const int*   rm1   = (const int*)d_in[5];
    const int*   rm2   = (const int*)d_in[6];
    float* out = (float*)d_out;

    prep_B_kernel<<<NKSTEPS, 256>>>(w, mask);
    prep_x_kernel<<<LEVELS * BATCH, 256>>>(x, rm0, rm1, rm2);
    transpose_mc_kernel<<<dim3(N_IN / 32, BATCH / 32, LEVELS), dim3(32, 8)>>>();
    main_kernel<<<dim3(MTILES, KSPLIT), 512>>>();
    reduce_kernel<<<(BATCH * N_OUT) / 256, 256>>>(gamma, out);
}

// round 6
// speedup vs baseline: 1.9471x; 1.1265x over previous
#include <cuda_runtime.h>
#include <cuda_fp16.h>
#include <cstdint>

// ---------------------------------------------------------------------------
// Problem constants
// ---------------------------------------------------------------------------
#define N_IN    8192
#define N_OUT   256
#define BATCH   1024
#define LEVELS  2
#define NKSTEPS (LEVELS * N_IN)               // 16384 ; kstep = (l,i), 16 k each
#define KSPLIT  18
#define KSTEPS_PER ((NKSTEPS + KSPLIT - 1) / KSPLIT)  // 911
#define MTILES  (BATCH / 128)                 // 8

// main-kernel pipeline
#define STAGES   5
#define STAGE_B  (8192 + 512)                 // B tile (256 j x 32B) + mc slice (128 x 4B)

// Scratch (__device__ globals: no runtime allocation)
// g_B[kstep][j][p] : p = permuted truth-table index so lane t's uint2 at byte
//                    8t is exactly the mma.m16n8k16 B fragment (b0,b1).
__device__ __half   g_B  [(size_t)NKSTEPS * N_OUT * 16];      // 134 MB
__device__ unsigned g_mc0[(size_t)LEVELS * BATCH * N_IN];     // [l][b][i] tmp
__device__ unsigned g_mcT[(size_t)LEVELS * N_IN * BATCH];     // [l][i][bperm]
__device__ float    g_part[(size_t)KSPLIT * BATCH * N_OUT];   // split-K partials

// ---------------------------------------------------------------------------
// prep_B: for kstep (l,i), thread j:  s[c] = sign(w[16l+c,i,j]) * mask[i,j]
// stored in permuted order {0,1,8,9, 2,3,10,11, 4,5,12,13, 6,7,14,15}.
// ---------------------------------------------------------------------------
__global__ void __launch_bounds__(256) prep_B_kernel(const float* __restrict__ w,
                                                     const float* __restrict__ mask) {
    const int ki = blockIdx.x;               // l*8192 + i
    const int l  = ki >> 13;
    const int i  = ki & (N_IN - 1);
    const int j  = threadIdx.x;
    const float m = mask[(size_t)i * N_OUT + j];
    float s[16];
#pragma unroll
    for (int c = 0; c < 16; ++c) {
        float v = w[((size_t)(16 * l + c) * N_IN + i) * N_OUT + j];
        s[c] = (v > 0.f) ? m : ((v < 0.f) ? -m : 0.f);
    }
    const int perm[16] = {0, 1, 8, 9, 2, 3, 10, 11, 4, 5, 12, 13, 6, 7, 14, 15};
    unsigned r[8];
#pragma unroll
    for (int p = 0; p < 8; ++p) {
        unsigned lo = __half_as_ushort(__float2half_rn(s[perm[2 * p]]));
        unsigned hi = __half_as_ushort(__float2half_rn(s[perm[2 * p + 1]]));
        r[p] = lo | (hi << 16);
    }
    uint4* d = (uint4*)(g_B + ((size_t)ki * N_OUT + j) * 16);
    d[0] = make_uint4(r[0], r[1], r[2], r[3]);
    d[1] = make_uint4(r[4], r[5], r[6], r[7]);
}

// ---------------------------------------------------------------------------
// prep_x: mc0[l][b][i] = (c<<16) | fp16(|s0*s1*s2*s3|)
// c = (s0<0)<<3 | (s1<0)<<2 | (s2<0)<<1 | (s3<0)
// ---------------------------------------------------------------------------
__global__ void __launch_bounds__(256) prep_x_kernel(const float* __restrict__ x,
                                                     const int* __restrict__ rm0,
                                                     const int* __restrict__ rm1,
                                                     const int* __restrict__ rm2) {
    int lb = blockIdx.x;
    const float* row = x + (size_t)lb * N_IN;
    unsigned* mp = g_mc0 + (size_t)lb * N_IN;
    for (int i = threadIdx.x; i < N_IN; i += blockDim.x) {
        float s0 = row[i];
        float s1 = row[rm0[i]];
        float s2 = row[rm1[i]];
        float s3 = row[rm2[i]];
        unsigned c = ((s0 < 0.f) ? 8u : 0u) | ((s1 < 0.f) ? 4u : 0u) |
                     ((s2 < 0.f) ? 2u : 0u) | ((s3 < 0.f) ? 1u : 0u);
        unsigned mh = __half_as_ushort(__float2half_rn(fabsf(s0 * s1 * s2 * s3)));
        mp[i] = (c << 16) | mh;
    }
}

// ---------------------------------------------------------------------------
// transpose mc0 [l][b][i] -> mcT [l][i][bperm],
// bperm = (b&~15) | ((b&7)<<1) | ((b>>3)&1)  (rows g and g+8 adjacent)
// ---------------------------------------------------------------------------
__global__ void __launch_bounds__(256) transpose_mc_kernel() {
    __shared__ unsigned tile[32][33];
    const int l  = blockIdx.z;
    const int b0 = blockIdx.y * 32;
    const int i0 = blockIdx.x * 32;
    const int tx = threadIdx.x, ty = threadIdx.y;
#pragma unroll
    for (int r = ty; r < 32; r += 8)
        tile[r][tx] = g_mc0[((size_t)l * BATCH + b0 + r) * N_IN + i0 + tx];
    __syncthreads();
#pragma unroll
    for (int r = ty; r < 32; r += 8) {
        int b  = b0 + tx;
        int bp = (b & ~15) | ((b & 7) << 1) | ((b >> 3) & 1);
        g_mcT[((size_t)l * N_IN + i0 + r) * BATCH + bp] = tile[tx][r];
    }
}

// ---------------------------------------------------------------------------
// HMMA main kernel. grid = (MTILES=8, KSPLIT=18); block = 512 (16 warps).
// CTA tile M=128 x N=256; warp tile 32(M) x 64(N)  (warp_m = warp&3, warp_n = warp>>2).
// 5-stage cp.async pipeline: per kstep, the CTA stages the full 8KB B tile +
// its 512B mc slice in smem; warps consume via conflict-free LDS.64.
// A fragments built in registers (one-hot over the truth table, 2 blks/warp).
// ---------------------------------------------------------------------------
__device__ __forceinline__ uint32_t smem_u32(const void* p) {
    return (uint32_t)__cvta_generic_to_shared(p);
}
#define CP_ASYNC16(dst, src) \
    asm volatile("cp.async.cg.shared.global [%0], [%1], 16;" :: "r"(dst), "l"(src) : "memory")
#define CP_COMMIT() asm volatile("cp.async.commit_group;" ::: "memory")
#define CP_WAIT(n)  asm volatile("cp.async.wait_group %0;" :: "n"(n) : "memory")

__device__ __forceinline__ void mma16816(float* d, unsigned a0, unsigned a1,
                                         unsigned a2, unsigned a3,
                                         unsigned b0, unsigned b1) {
    asm volatile(
        "mma.sync.aligned.m16n8k16.row.col.f32.f16.f16.f32 "
        "{%0,%1,%2,%3}, {%4,%5,%6,%7}, {%8,%9}, {%0,%1,%2,%3};"
        : "+f"(d[0]), "+f"(d[1]), "+f"(d[2]), "+f"(d[3])
        : "r"(a0), "r"(a1), "r"(a2), "r"(a3), "r"(b0), "r"(b1));
}

__global__ void __launch_bounds__(512, 1) main_kernel() {
    __shared__ __align__(16) unsigned char sm[STAGES * STAGE_B];
    const uint32_t smb = smem_u32(sm);

    const int tid  = threadIdx.x;
    const int warp = tid >> 5, lane = tid & 31;
    const int g = lane >> 2, t = lane & 3;
    const int warp_m = warp & 3, warp_n = warp >> 2;
    const int bm0 = blockIdx.x * 128;                // CTA batch-row base
    const int jn  = warp_n * 64;                     // warp out-col base
    const int ks0 = blockIdx.y * KSTEPS_PER;
    const int nk  = min(NKSTEPS, ks0 + KSTEPS_PER) - ks0;

    float acc[2][8][4];
#pragma unroll
    for (int a = 0; a < 2; ++a)
#pragma unroll
        for (int b = 0; b < 8; ++b)
#pragma unroll
            for (int d = 0; d < 4; ++d) acc[a][b][d] = 0.f;

    // producer addresses for this thread
    const char* srcB0 = (const char*)g_B + (size_t)ks0 * 8192 + tid * 16;
    const unsigned* srcM0 = g_mcT + (size_t)ks0 * BATCH + bm0 + tid * 4;  // tid<32

    auto fill = [&](int it, int slot) {
        if (it < nk) {
            uint32_t st = smb + slot * STAGE_B;
            CP_ASYNC16(st + tid * 16, srcB0 + (size_t)it * 8192);
            if (tid < 32)
                CP_ASYNC16(st + 8192 + tid * 16, (const char*)(srcM0 + (size_t)it * BATCH));
        }
        CP_COMMIT();
    };

    // prologue: fill stages 0..3 (ksteps 0..3)
#pragma unroll
    for (int p = 0; p < STAGES - 1; ++p) fill(p, p);

    // consumer smem offsets
    const uint32_t bOff  = ((uint32_t)(jn + g) << 5) + ((uint32_t)t << 3);
    const uint32_t mOff  = 8192u + (((uint32_t)warp_m * 32 + 2 * g) << 2);

    int cslot = 0, fslot = STAGES - 1;
    for (int it = 0; it < nk; ++it) {
        CP_WAIT(STAGES - 2);
        __syncthreads();
        const uint32_t st = smb + cslot * STAGE_B;

        uint2 B[8];
#pragma unroll
        for (int f = 0; f < 8; ++f)
            asm volatile("ld.shared.v2.u32 {%0,%1}, [%2];"
                         : "=r"(B[f].x), "=r"(B[f].y) : "r"(st + bOff + f * 256));
        uint2 Mc[2];
#pragma unroll
        for (int blk = 0; blk < 2; ++blk)
            asm volatile("ld.shared.v2.u32 {%0,%1}, [%2];"
                         : "=r"(Mc[blk].x), "=r"(Mc[blk].y) : "r"(st + mOff + blk * 64));

        // refill next stage while MMAs run
        fill(it + STAGES - 1, fslot);

#pragma unroll
        for (int blk = 0; blk < 2; ++blk) {
            unsigned m0 = Mc[blk].x, m1 = Mc[blk].y;   // rows g, g+8
            unsigned c0 = m0 >> 16,  c1 = m1 >> 16;
            unsigned v0 = (c0 & 1u) ? (m0 << 16) : (m0 & 0xFFFFu);
            unsigned v1 = (c1 & 1u) ? (m1 << 16) : (m1 & 0xFFFFu);
            unsigned h0 = c0 >> 1,   h1 = c1 >> 1;
            unsigned a0 = (h0 == (unsigned)t)       ? v0 : 0u;
            unsigned a1 = (h1 == (unsigned)t)       ? v1 : 0u;
            unsigned a2 = (h0 == (unsigned)(t + 4)) ? v0 : 0u;
            unsigned a3 = (h1 == (unsigned)(t + 4)) ? v1 : 0u;
#pragma unroll
            for (int f = 0; f < 8; ++f)
                mma16816(acc[blk][f], a0, a1, a2, a3, B[f].x, B[f].y);
        }

        if (++cslot == STAGES) cslot = 0;
        if (++fslot == STAGES) fslot = 0;
    }

    // Epilogue: split-K partial tile (no atomics).
    float* pp = g_part + (size_t)blockIdx.y * BATCH * N_OUT;
#pragma unroll
    for (int blk = 0; blk < 2; ++blk) {
        int r0 = bm0 + warp_m * 32 + blk * 16 + g, r1 = r0 + 8;
#pragma unroll
        for (int f = 0; f < 8; ++f) {
            int j0 = jn + f * 8 + 2 * t;
            *(float2*)&pp[(size_t)r0 * N_OUT + j0] =
                make_float2(acc[blk][f][0], acc[blk][f][1]);
            *(float2*)&pp[(size_t)r1 * N_OUT + j0] =
                make_float2(acc[blk][f][2], acc[blk][f][3]);
        }
    }
}

// ---------------------------------------------------------------------------
// reduce: out = |gamma| * sum over KSPLIT partials
// ---------------------------------------------------------------------------
__global__ void __launch_bounds__(256) reduce_kernel(const float* __restrict__ gamma,
                                                     float* __restrict__ out) {
    size_t idx = (size_t)blockIdx.x * 256 + threadIdx.x;
    float s = 0.f;
#pragma unroll
    for (int p = 0; p < KSPLIT; ++p)
        s += g_part[(size_t)p * BATCH * N_OUT + idx];
    out[idx] = s * fabsf(gamma[0]);
}

// ---------------------------------------------------------------------------
// launch — inputs: x f32[2,1024,8192], w f32[32,8192,256], gamma f32[1],
// pruning_mask f32[8192,256], rand_map_0/1/2 i32[8192]. out f32[1024,256].
// ---------------------------------------------------------------------------
extern "C" void kernel_launch(void* const* d_in, const int* in_sizes, int n_in,
                              void* d_out, int out_size) {
    const float* x     = (const float*)d_in[0];
    const float* w     = (const float*)d_in[1];
    const float* gamma = (const float*)d_in[2];
    const float* mask  = (const float*)d_in[3];
    const int*   rm0   = (const int*)d_in[4];
    const int*   rm1   = (const int*)d_in[5];
    const int*   rm2   = (const int*)d_in[6];
    float* out = (float*)d_out;

    prep_B_kernel<<<NKSTEPS, 256>>>(w, mask);
    prep_x_kernel<<<LEVELS * BATCH, 256>>>(x, rm0, rm1, rm2);
    transpose_mc_kernel<<<dim3(N_IN / 32, BATCH / 32, LEVELS), dim3(32, 8)>>>();
    main_kernel<<<dim3(MTILES, KSPLIT), 512>>>();
    reduce_kernel<<<(BATCH * N_OUT) / 256, 256>>>(gamma, out);
}